// round 15
// baseline (speedup 1.0000x reference)
#include <cuda_runtime.h>
#include <math.h>

// EyesMouthLoss: mean(|pred-target| * (1 + priority*299))
//
// R12 decomposition (exact):
//   N*mean = sum_all |d|  +  sum_{p in union of landmark disks} (w(p)-1)*s(p)
// where s(p) = sum_c |pred-target|, and w deviates from 1 only within 15px of
// a landmark (512 boxes of <=29x29 px ~= 1.6% of pixels).
//   - Streaming blocks: pure grid-stride float4 sum, zero weight machinery
//     (the weight code in the load path was capping DRAM at ~65% in R7-R11).
//   - Correction blocks (one per (image,landmark)): iterate the clipped box,
//     ownership = lowest-index containing box (exact overlap dedup), compute
//     w from all 32 landmarks, re-read 6 values, accumulate (w-1)*s.
//     Exactness: centers clamped to ints, pixels ints -> d^2<225 implies
//     |dx|<=14 and |dy|<=14, so the +/-14 box covers the full disk.
// Single kernel, block-specialized; both paths REDG into out[0]; out zeroed
// by an async memset graph node.

#define H 512
#define W 512
#define C 3
#define B 16
#define NCORR (B * 32)             // 512 correction blocks
#define NSTREAM 2048
#define NBLK (NCORR + NSTREAM)
#define THREADS 256
#define NV4 (B * C * H * W / 4)    // 3,145,728 float4s per array
#define SSTRIDE (NSTREAM * THREADS)       // 524,288 -> exactly 6 iters
#define RADIUS2 225.0f
#define INV_R (1.0f / 15.0f)
#define INV_N (1.0f / (16.0f * 3.0f * 512.0f * 512.0f))
#define FULL 0xFFFFFFFFu

__global__ void __launch_bounds__(THREADS, 6) eml_main(
    const float* __restrict__ pred,
    const float* __restrict__ target,
    const int*   __restrict__ lm,
    float* __restrict__ out)
{
    const int tid = threadIdx.x;
    float acc = 0.0f;

    if (blockIdx.x >= NCORR) {
        // ================= streaming path: pure float4 |diff| sum ==========
        const float4* __restrict__ p4 = (const float4*)pred;
        const float4* __restrict__ t4 = (const float4*)target;
        int i = (blockIdx.x - NCORR) * THREADS + tid;
#pragma unroll
        for (int k = 0; k < NV4 / SSTRIDE; k++) {
            const float4 pv = p4[i];
            const float4 tv = t4[i];
            acc += fabsf(pv.x - tv.x) + fabsf(pv.y - tv.y)
                 + fabsf(pv.z - tv.z) + fabsf(pv.w - tv.w);
            i += SSTRIDE;
        }
    } else {
        // ================= correction path: (w-1)*s over owned box pixels ==
        const int b = blockIdx.x >> 5;          // image
        const int L = blockIdx.x & 31;          // local landmark 0..31 (lm 36+L)

        __shared__ float s_cx[32], s_cy[32];
        if (tid < 32) {
            const int2 lxy = ((const int2*)lm)[b * 68 + 36 + tid];
            s_cx[tid] = (float)min(max(lxy.x, 0), W - 1);
            s_cy[tid] = (float)min(max(lxy.y, 0), H - 1);
        }
        __syncthreads();

        const int cxi = (int)s_cx[L];
        const int cyi = (int)s_cy[L];
        const int xlo = max(cxi - 14, 0), xhi = min(cxi + 14, W - 1);
        const int ylo = max(cyi - 14, 0), yhi = min(cyi + 14, H - 1);
        const int bw  = xhi - xlo + 1;
        const int npx = bw * (yhi - ylo + 1);

        for (int idx = tid; idx < npx; idx += THREADS) {
            const int x = xlo + (idx % bw);
            const int y = ylo + (idx / bw);
            const float xf = (float)x, yf = (float)y;

            // ownership: skip if an earlier landmark's box contains (x,y)
            bool owner = true;
            for (int j = 0; j < L; j++) {
                if (fabsf(xf - s_cx[j]) <= 14.0f && fabsf(yf - s_cy[j]) <= 14.0f) {
                    owner = false; break;
                }
            }
            if (!owner) continue;

            // full weight from all 32 landmarks
            float emn = 3.0e8f, mmn = 3.0e8f;
#pragma unroll
            for (int j = 0; j < 12; j++) {
                const float dx = xf - s_cx[j], dyy = yf - s_cy[j];
                emn = fminf(emn, fmaf(dx, dx, dyy * dyy));
            }
#pragma unroll
            for (int j = 12; j < 32; j++) {
                const float dx = xf - s_cx[j], dyy = yf - s_cy[j];
                mmn = fminf(mmn, fmaf(dx, dx, dyy * dyy));
            }
            const float e = (emn < RADIUS2) ? (1.0f - sqrtf(emn) * INV_R) : 0.0f;
            const float m = (mmn < RADIUS2) ? (1.0f - sqrtf(mmn) * INV_R) : 0.0f;
            const float p = fminf(e + m, 1.0f);
            if (p <= 0.0f) continue;

            // s(p) = sum_c |pred - target| at (b, y, x)
            const size_t off0 = ((size_t)b * C * H + (size_t)y) * W + x;
            float s = 0.0f;
#pragma unroll
            for (int c = 0; c < C; c++) {
                const size_t off = off0 + (size_t)c * (H * W);
                s += fabsf(pred[off] - target[off]);
            }
            acc = fmaf(p * 299.0f, s, acc);     // (w-1)*s
        }
    }

    // ---- block reduce + REDG ----
#pragma unroll
    for (int s = 16; s > 0; s >>= 1)
        acc += __shfl_xor_sync(FULL, acc, s);

    __shared__ float s_part[THREADS / 32];
    if ((tid & 31) == 0) s_part[tid >> 5] = acc;
    __syncthreads();

    if (tid == 0) {
        float bs = 0.0f;
#pragma unroll
        for (int wsl = 0; wsl < THREADS / 32; wsl++) bs += s_part[wsl];
        atomicAdd(out, bs * INV_N);   // fire-and-forget REDG
    }
}

extern "C" void kernel_launch(void* const* d_in, const int* in_sizes, int n_in,
                              void* d_out, int out_size)
{
    const float* pred   = (const float*)d_in[0];
    const float* target = (const float*)d_in[1];
    const int*   lmk    = (const int*)d_in[2];
    float* out = (float*)d_out;

    cudaMemsetAsync(out, 0, sizeof(float), 0);   // memset node, graph-capturable
    eml_main<<<NBLK, THREADS>>>(pred, target, lmk, out);
}